// round 12
// baseline (speedup 1.0000x reference)
#include <cuda_runtime.h>
#include <cstdint>

#define Bn 4096
#define Tn 5
#define Vn 8192
#define En 32
#define Hn 512
#define On 1024

// packed f16x2 words, fragment order: word s in 32k-chunk, kw=(s>>2)+(s&3)*4
__device__ __align__(16) uint32_t d_Xp[Tn * Bn * 16];
__device__ __align__(16) float    d_hA[Bn * Hn];
__device__ __align__(16) float    d_hB[Bn * Hn];
__device__ __align__(16) uint32_t d_hpA[Bn * 256];
__device__ __align__(16) uint32_t d_hpB[Bn * 256];
__device__ __align__(16) uint32_t d_hlnp[Bn * 256];
__device__ __align__(16) uint32_t d_pWhh[16 * 3 * 512 * 16];
__device__ __align__(16) uint32_t d_pWih[3 * 512 * 16];
__device__ __align__(16) uint32_t d_pEmb[256 * 32 * 16];
__device__ __align__(16) uint32_t d_pFc[16 * 1024 * 16];
__device__ __align__(16) float    d_pBias[4 * Hn];
__device__ __align__(16) float    d_embP[2 * 16384 * 32];
__device__ __align__(16) float    d_h1[Hn];        // uniform h after step 0
__device__ __align__(16) float    d_gh1[3 * Hn];   // Whh @ h1 (uniform)

__device__ __forceinline__ uint32_t f2h2(float lo, float hi) {
    uint32_t r; asm volatile("cvt.rn.f16x2.f32 %0, %1, %2;" : "=r"(r) : "f"(hi), "f"(lo));
    return r;
}
__device__ __forceinline__ void mmah(float c[4], uint32_t a0, uint32_t a1, uint32_t a2,
                                     uint32_t a3, uint32_t b0, uint32_t b1) {
    asm volatile(
        "mma.sync.aligned.m16n8k16.row.col.f32.f16.f16.f32 "
        "{%0,%1,%2,%3}, {%4,%5,%6,%7}, {%8,%9}, {%0,%1,%2,%3};"
        : "+f"(c[0]), "+f"(c[1]), "+f"(c[2]), "+f"(c[3])
        : "r"(a0), "r"(a1), "r"(a2), "r"(a3), "r"(b0), "r"(b1));
}
__device__ __forceinline__ float sigm(float x) { return 1.f / (1.f + __expf(-x)); }
__device__ __forceinline__ float tanh_fast(float x) { return 1.f - 2.f / (1.f + __expf(2.f * x)); }
__device__ __forceinline__ void cp16(uint32_t dst, const void* src) {
    asm volatile("cp.async.cg.shared.global [%0], [%1], 16;" :: "r"(dst), "l"(src));
}
__device__ __forceinline__ void cp_commit() { asm volatile("cp.async.commit_group;"); }
template <int N> __device__ __forceinline__ void cp_wait() {
    asm volatile("cp.async.wait_group %0;" :: "n"(N));
}
__device__ __forceinline__ uint32_t smem_u32(const void* p) {
    return (uint32_t)__cvta_generic_to_shared(p);
}
__device__ __forceinline__ int sofkw(int kw) { return (kw & 3) * 4 + (kw >> 2); }

// ---------------- fused pack ----------------------------------------------------
#define NWHH (16 * 3 * 512 * 16)
#define NWIH (3 * 512 * 16)
#define NEMB (256 * 32 * 16)
#define NFC  (16 * 1024 * 16)
__global__ void pack_all(const float* __restrict__ Whh, const float* __restrict__ Wih,
                         const float* __restrict__ embW, const float* __restrict__ fcW,
                         const float* __restrict__ bih, const float* __restrict__ bhh) {
    int idx = blockIdx.x * 256 + threadIdx.x;
    if (idx < NWHH) {
        int s = idx & 15; int n = (idx >> 4) & 511; int u = idx >> 13;
        int gt = u % 3, it = u / 3;
        int kw = (s >> 2) + (s & 3) * 4; int k = it * 32 + 2 * kw;
        const float* p = Whh + (size_t)(gt * Hn + n) * Hn + k;
        d_pWhh[idx] = f2h2(p[0], p[1]);
    } else if (idx < NWHH + NWIH) {
        int i2 = idx - NWHH;
        int s = i2 & 15; int n = (i2 >> 4) & 511; int gt = i2 >> 13;
        int kw = (s >> 2) + (s & 3) * 4;
        const float* p = Wih + (size_t)(gt * Hn + n) * En + 2 * kw;
        d_pWih[i2] = f2h2(p[0], p[1]);
    } else if (idx < NWHH + NWIH + NEMB) {
        int i2 = idx - (NWHH + NWIH);
        int s = i2 & 15; int n = (i2 >> 4) & 31; int it = i2 >> 9;
        int kw = (s >> 2) + (s & 3) * 4; int k = it * 32 + 2 * kw;
        const float* p = embW + (size_t)n * Vn + k;
        d_pEmb[i2] = f2h2(p[0], p[1]);
    } else if (idx < NWHH + NWIH + NEMB + NFC) {
        int i2 = idx - (NWHH + NWIH + NEMB);
        int s = i2 & 15; int n = (i2 >> 4) & 1023; int it = i2 >> 14;
        int kw = (s >> 2) + (s & 3) * 4; int k = it * 32 + 2 * kw;
        const float* p = fcW + (size_t)n * Hn + k;
        d_pFc[i2] = f2h2(p[0], p[1]);
    } else if (idx < NWHH + NWIH + NEMB + NFC + 4 * Hn) {
        int i2 = idx - (NWHH + NWIH + NEMB + NFC);
        int j = i2 & 511, wh = i2 >> 9;
        d_pBias[i2] = (wh == 0) ? bih[j] + bhh[j]
                    : (wh == 1) ? bih[Hn + j] + bhh[Hn + j]
                    : (wh == 2) ? bih[2 * Hn + j] : bhh[2 * Hn + j];
    }
}

// ---------------- step 0: h1 (batch-uniform 512-vector), all f32 ------------------
__global__ void __launch_bounds__(512) step0_kernel(
    const float* __restrict__ init_emb, const float* __restrict__ eg,
    const float* __restrict__ ebeta, const float* __restrict__ Wih,
    const float* __restrict__ bih, const float* __restrict__ bhh) {
    __shared__ float x0[32];
    int tid = threadIdx.x;
    if (tid < 32) {
        float v = init_emb[tid];
        float s = v, sq = v * v;
        #pragma unroll
        for (int o = 16; o; o >>= 1) {
            s += __shfl_xor_sync(~0u, s, o); sq += __shfl_xor_sync(~0u, sq, o);
        }
        float m = s / 32.f, rs = rsqrtf(sq / 32.f - m * m + 1e-5f);
        x0[tid] = (v - m) * rs * eg[tid] + ebeta[tid];
    }
    __syncthreads();
    int j = tid;
    float gr = 0.f, gz = 0.f, gn = 0.f;
    #pragma unroll
    for (int k = 0; k < 32; k++) {
        float xv = x0[k];
        gr += Wih[(size_t)j * En + k] * xv;
        gz += Wih[(size_t)(Hn + j) * En + k] * xv;
        gn += Wih[(size_t)(2 * Hn + j) * En + k] * xv;
    }
    float r_ = sigm(gr + bih[j] + bhh[j]);
    float z_ = sigm(gz + bih[Hn + j] + bhh[Hn + j]);
    float n_ = tanh_fast(gn + bih[2 * Hn + j] + r_ * bhh[2 * Hn + j]);
    d_h1[j] = (1.f - z_) * n_;
}

// ---------------- gh1 = Whh @ h1 (1536x512 f32 GEMV, warp per row) ------------------
__global__ void __launch_bounds__(256) gh1_kernel(const float* __restrict__ Whh) {
    int row = blockIdx.x * 8 + (threadIdx.x >> 5);   // 0..1535
    int lane = threadIdx.x & 31;
    const float* wr = Whh + (size_t)row * Hn;
    float s = 0.f;
    #pragma unroll
    for (int i = 0; i < 4; i++) {
        float4 w = *(const float4*)(wr + lane * 4 + i * 128);
        float4 h = *(const float4*)(d_h1 + lane * 4 + i * 128);
        s += w.x * h.x + w.y * h.y + w.z * h.z + w.w * h.w;
    }
    #pragma unroll
    for (int o = 16; o; o >>= 1) s += __shfl_xor_sync(~0u, s, o);
    if (lane == 0) d_gh1[row] = s;
}

// ---------------- embed: zero-smem zero-sync streaming LDG GEMM ---------------------
// K-split x2, BM=128 (8 warps x 16m), 256 thr. A: direct LDG.64 frags (no reuse),
// B: direct LDG.128 frags (L1-served, tiny). Register double-buffered.
__global__ void __launch_bounds__(256) embed_kernel(const float* __restrict__ msg) {
    const int tid = threadIdx.x, warp = tid >> 5, lane = tid & 31;
    const int gq = lane >> 2, tq = lane & 3;
    const int ks = blockIdx.x;
    const int m0 = blockIdx.y * 128 + warp * 16;
    const int mr0 = m0 + gq, mr1 = mr0 + 8;
    const float* pA0 = msg + ((size_t)(mr0 >> 2) * Tn + (mr0 & 3)) * Vn + ks * 4096 + 2 * tq;
    const float* pA1 = msg + ((size_t)(mr1 >> 2) * Tn + (mr1 & 3)) * Vn + ks * 4096 + 2 * tq;
    const uint32_t* pB = d_pEmb + (size_t)ks * 128 * 32 * 16 + (size_t)gq * 16 + tq * 4;

    float2 aA[8], aB[8];
    uint4  bA[4], bB[4];
    float  acc[4][4] = {};

    auto loadA = [&](int it, float2* a) {
        int o = it * 32;
        a[0] = *(const float2*)(pA0 + o);      a[1] = *(const float2*)(pA1 + o);
        a[2] = *(const float2*)(pA0 + o + 8);  a[3] = *(const float2*)(pA1 + o + 8);
        a[4] = *(const float2*)(pA0 + o + 16); a[5] = *(const float2*)(pA1 + o + 16);
        a[6] = *(const float2*)(pA0 + o + 24); a[7] = *(const float2*)(pA1 + o + 24);
    };
    auto loadB = [&](int it, uint4* b) {
        #pragma unroll
        for (int nb = 0; nb < 4; nb++)
            b[nb] = *(const uint4*)(pB + ((size_t)it * 32 + nb * 8) * 16);
    };
    auto comp = [&](const float2* a, const uint4* b) {
        #pragma unroll
        for (int s = 0; s < 2; s++) {
            uint32_t a0 = f2h2(a[4 * s + 0].x, a[4 * s + 0].y);
            uint32_t a1 = f2h2(a[4 * s + 1].x, a[4 * s + 1].y);
            uint32_t a2 = f2h2(a[4 * s + 2].x, a[4 * s + 2].y);
            uint32_t a3 = f2h2(a[4 * s + 3].x, a[4 * s + 3].y);
            #pragma unroll
            for (int nb = 0; nb < 4; nb++)
                mmah(acc[nb], a0, a1, a2, a3,
                     s ? b[nb].z : b[nb].x, s ? b[nb].w : b[nb].y);
        }
    };

    loadA(0, aA); loadB(0, bA);
    #pragma unroll 1
    for (int it = 0; it < 128; it += 2) {
        loadA(it + 1, aB); loadB(it + 1, bB);
        comp(aA, bA);
        if (it + 2 < 128) { loadA(it + 2, aA); loadB(it + 2, bA); }
        comp(aB, bB);
    }

    float* dst = d_embP + (size_t)ks * 16384 * 32;
    #pragma unroll
    for (int nb = 0; nb < 4; nb++) {
        int col = nb * 8 + 2 * tq;
        *(float2*)&dst[(size_t)mr0 * 32 + col] = make_float2(acc[nb][0], acc[nb][1]);
        *(float2*)&dst[(size_t)mr1 * 32 + col] = make_float2(acc[nb][2], acc[nb][3]);
    }
}

// ---------------- lnx: sum 2 partials + bias + LN + pack ---------------------------
__global__ void __launch_bounds__(256) lnx_kernel(const float* __restrict__ eb,
                                                  const float* __restrict__ gw,
                                                  const float* __restrict__ bw) {
    int row = blockIdx.x * 8 + (threadIdx.x >> 5);
    int lane = threadIdx.x & 31;
    float v = d_embP[(size_t)row * 32 + lane]
            + d_embP[(size_t)16384 * 32 + (size_t)row * 32 + lane] + eb[lane];
    float s = v, sq = v * v;
    #pragma unroll
    for (int o = 16; o; o >>= 1) {
        s += __shfl_xor_sync(~0u, s, o); sq += __shfl_xor_sync(~0u, sq, o);
    }
    float m = s / 32.f, rs = rsqrtf(sq / 32.f - m * m + 1e-5f);
    float o1 = (v - m) * rs * gw[lane] + bw[lane];
    float o2 = __shfl_down_sync(~0u, o1, 1);
    if (!(lane & 1)) {
        int bb = row >> 2, tt = row & 3;
        d_Xp[((size_t)(tt + 1) * Bn + bb) * 16 + sofkw(lane >> 1)] = f2h2(o1, o2);
    }
}

// ---------------- GRU fp16 (t = 1..4): BM=64, BN=64x3, 256 thr, 4-stage, 1 sync -----
__global__ void __launch_bounds__(256, 2) gru_kernel(int t) {
    extern __shared__ uint32_t sm[];
    const uint32_t smb = smem_u32(sm);
    const int tid = threadIdx.x, warp = tid >> 5, lane = tid & 31;
    const int gq = lane >> 2, tq = lane & 3;
    const int n0 = blockIdx.x * 64, m0 = blockIdx.y * 64;
    const int mo = (warp & 1) * 32, no = (warp >> 1) * 16;
    const float*    hold  = (t & 1) ? d_hB  : d_hA;
    float*          hnew  = (t & 1) ? d_hA  : d_hB;
    const uint32_t* hpold = (t & 1) ? d_hpB : d_hpA;
    uint32_t*       hpnew = (t & 1) ? d_hpA : d_hpB;
    const int NITER = (t == 1) ? 1 : 17;

    const int arow = tid >> 2, acc4 = tid & 3;

    auto prefetch0 = [&]() {
        uint32_t base = smb;
        cp16(base + arow * 64 + acc4 * 16,
             d_Xp + ((size_t)t * Bn + m0 + arow) * 16 + acc4 * 4);
        #pragma unroll
        for (int j = 0; j < 3; j++) {
            int id = tid + j * 256;
            int brow = id >> 2, cc = id & 3;
            int gt = brow >> 6, row = brow & 63;
            cp16(base + 4096 + brow * 64 + cc * 16,
                 d_pWih + ((size_t)gt * Hn + n0 + row) * 16 + cc * 4);
        }
        cp_commit();
    };
    auto prefetchH = [&](int it) {
        uint32_t base = smb + (it & 3) * 16384;
        cp16(base + arow * 64 + acc4 * 16,
             hpold + (size_t)(m0 + arow) * 256 + (it - 1) * 16 + acc4 * 4);
        #pragma unroll
        for (int j = 0; j < 3; j++) {
            int id = tid + j * 256;
            int brow = id >> 2, cc = id & 3;
            int gt = brow >> 6, row = brow & 63;
            cp16(base + 4096 + brow * 64 + cc * 16,
                 d_pWhh + (((size_t)(it - 1) * 3 + gt) * Hn + n0 + row) * 16 + cc * 4);
        }
        cp_commit();
    };

    float ar[2][2][4] = {}, az[2][2][4] = {}, anx[2][2][4] = {}, anh[2][2][4] = {};
    prefetch0();
    if (NITER > 1) { prefetchH(1); prefetchH(2); }
    for (int it = 0; it < NITER; ++it) {
        int rem = NITER - 1 - it;
        if (rem >= 2) cp_wait<2>(); else if (rem == 1) cp_wait<1>(); else cp_wait<0>();
        __syncthreads();
        if (it + 3 < NITER) prefetchH(it + 3);
        const uint32_t* A = sm + (it & 3) * 4096;
        const uint32_t* B = A + 1024;
        uint4 Af[4];
        Af[0] = *(const uint4*)&A[(mo + gq) * 16 + tq * 4];
        Af[1] = *(const uint4*)&A[(mo + gq + 8) * 16 + tq * 4];
        Af[2] = *(const uint4*)&A[(mo + 16 + gq) * 16 + tq * 4];
        Af[3] = *(const uint4*)&A[(mo + 24 + gq) * 16 + tq * 4];
        auto dog = [&](float (&acc)[2][2][4], int g) {
            #pragma unroll
            for (int nb = 0; nb < 2; nb++) {
                uint4 Bf = *(const uint4*)&B[(g * 64 + no + nb * 8 + gq) * 16 + tq * 4];
                mmah(acc[0][nb], Af[0].x, Af[1].x, Af[0].y, Af[1].y, Bf.x, Bf.y);
                mmah(acc[1][nb], Af[2].x, Af[3].x, Af[2].y, Af[3].y, Bf.x, Bf.y);
                mmah(acc[0][nb], Af[0].z, Af[1].z, Af[0].w, Af[1].w, Bf.z, Bf.w);
                mmah(acc[1][nb], Af[2].z, Af[3].z, Af[2].w, Af[3].w, Bf.z, Bf.w);
            }
        };
        dog(ar, 0); dog(az, 1);
        if (it == 0) dog(anx, 2); else dog(anh, 2);
    }

    #pragma unroll
    for (int mf = 0; mf < 2; ++mf)
    #pragma unroll
    for (int nb = 0; nb < 2; ++nb) {
        int j0 = n0 + no + nb * 8 + 2 * tq;
        int kw = (j0 & 31) >> 1, sw = sofkw(kw), ch = j0 >> 5;
        #pragma unroll
        for (int half = 0; half < 2; ++half) {
            int brow = m0 + mo + mf * 16 + gq + half * 8;
            float hv[2];
            #pragma unroll
            for (int c2 = 0; c2 < 2; ++c2) {
                int idx = half * 2 + c2, j = j0 + c2;
                float ghr = 0.f, ghz = 0.f, ghn = 0.f, hprev;
                if (t == 1) {
                    ghr = d_gh1[j]; ghz = d_gh1[Hn + j]; ghn = d_gh1[2 * Hn + j];
                    hprev = d_h1[j];
                } else {
                    hprev = hold[(size_t)brow * Hn + j];
                }
                float r_ = sigm(ar[mf][nb][idx] + d_pBias[j] + ghr);
                float z_ = sigm(az[mf][nb][idx] + d_pBias[Hn + j] + ghz);
                float n_ = tanh_fast(anx[mf][nb][idx] + d_pBias[2 * Hn + j]
                                     + r_ * (anh[mf][nb][idx] + d_pBias[3 * Hn + j] + ghn));
                hv[c2] = (1.f - z_) * n_ + z_ * hprev;
                hnew[(size_t)brow * Hn + j] = hv[c2];
            }
            hpnew[(size_t)brow * 256 + ch * 16 + sw] = f2h2(hv[0], hv[1]);
        }
    }
}

// ---------------- LN(h_last) -> packed f16 ------------------------------------------
__global__ void __launch_bounds__(256) hln_kernel(const float* __restrict__ g,
                                                  const float* __restrict__ be) {
    int row = blockIdx.x * 8 + (threadIdx.x >> 5);
    int lane = threadIdx.x & 31;
    const float* hp = d_hB + (size_t)row * Hn;
    float4 v[4]; float s = 0.f, sq = 0.f;
    #pragma unroll
    for (int i = 0; i < 4; i++) {
        v[i] = *(const float4*)(hp + lane * 4 + i * 128);
        s += v[i].x + v[i].y + v[i].z + v[i].w;
        sq += v[i].x * v[i].x + v[i].y * v[i].y + v[i].z * v[i].z + v[i].w * v[i].w;
    }
    #pragma unroll
    for (int o = 16; o; o >>= 1) {
        s += __shfl_xor_sync(~0u, s, o); sq += __shfl_xor_sync(~0u, sq, o);
    }
    float m = s / 512.f, rs = rsqrtf(sq / 512.f - m * m + 1e-5f);
    uint32_t* op = d_hlnp + (size_t)row * 256;
    #pragma unroll
    for (int i = 0; i < 4; i++) {
        int c = lane * 4 + i * 128;
        int ch = c >> 5;
        float o0 = (v[i].x - m) * rs * g[c] + be[c];
        float o1 = (v[i].y - m) * rs * g[c + 1] + be[c + 1];
        float o2 = (v[i].z - m) * rs * g[c + 2] + be[c + 2];
        float o3 = (v[i].w - m) * rs * g[c + 3] + be[c + 3];
        int kw = (c & 31) >> 1;
        op[ch * 16 + sofkw(kw)]     = f2h2(o0, o1);
        op[ch * 16 + sofkw(kw + 1)] = f2h2(o2, o3);
    }
}

// ---------------- fc fp16: BM=128, BN=64, 256 thr, 3-stage, 1 sync -------------------
__global__ void __launch_bounds__(256, 1) fc_kernel(const float* __restrict__ bias,
                                                    float* __restrict__ out) {
    extern __shared__ uint32_t sm[];
    const uint32_t smb = smem_u32(sm);
    const int tid = threadIdx.x, warp = tid >> 5, lane = tid & 31;
    const int gq = lane >> 2, tq = lane & 3;
    const int n0 = blockIdx.x * 64, m0 = blockIdx.y * 128;
    const int mo = (warp & 3) * 32, no = (warp >> 2) * 32;

    auto prefetch = [&](int it) {
        uint32_t base = smb + (it % 3) * 12288;
        #pragma unroll
        for (int j = 0; j < 2; j++) {
            int id = tid + j * 256; int row = id >> 2, cc = id & 3;
            cp16(base + row * 64 + cc * 16,
                 d_hlnp + (size_t)(m0 + row) * 256 + it * 16 + cc * 4);
        }
        { int row = tid >> 2, cc = tid & 3;
          cp16(base + 8192 + row * 64 + cc * 16,
               d_pFc + ((size_t)it * On + n0 + row) * 16 + cc * 4); }
        cp_commit();
    };

    float acc[2][4][4] = {};
    prefetch(0); prefetch(1);
    for (int it = 0; it < 16; ++it) {
        if (it <= 13) cp_wait<1>(); else cp_wait<0>();
        __syncthreads();
        if (it + 2 < 16) prefetch(it + 2);
        const uint32_t* A = sm + (it % 3) * 3072;
        const uint32_t* B = A + 2048;
        uint4 Af[4];
        Af[0] = *(const uint4*)&A[(mo + gq) * 16 + tq * 4];
        Af[1] = *(const uint4*)&A[(mo + gq + 8) * 16 + tq * 4];
        Af[2] = *(const uint4*)&A[(mo + 16 + gq) * 16 + tq * 4];
        Af[3] = *(const uint4*)&A[(mo + 24 + gq) * 16 + tq * 4];
        #pragma unroll
        for (int nb = 0; nb < 4; nb++) {
            uint4 Bf = *(const uint4*)&B[(no + nb * 8 + gq) * 16 + tq * 4];
            mmah(acc[0][nb], Af[0].x, Af[1].x, Af[0].y, Af[1].y, Bf.x, Bf.y);
            mmah(acc[1][nb], Af[2].x, Af[3].x, Af[2].y, Af[3].y, Bf.x, Bf.y);
            mmah(acc[0][nb], Af[0].z, Af[1].z, Af[0].w, Af[1].w, Bf.z, Bf.w);
            mmah(acc[1][nb], Af[2].z, Af[3].z, Af[2].w, Af[3].w, Bf.z, Bf.w);
        }
    }
    #pragma unroll
    for (int mf = 0; mf < 2; ++mf)
    #pragma unroll
    for (int nb = 0; nb < 4; ++nb)
    #pragma unroll
    for (int idx = 0; idx < 4; ++idx) {
        int row = m0 + mo + mf * 16 + gq + (idx >> 1) * 8;
        int j = n0 + no + nb * 8 + 2 * tq + (idx & 1);
        out[(size_t)row * On + j] = sigm(acc[mf][nb][idx] + bias[j]);
    }
}

// ---------------- launch --------------------------------------------------------------
extern "C" void kernel_launch(void* const* d_in, const int* in_sizes, int n_in,
                              void* d_out, int out_size) {
    const float* msg      = (const float*)d_in[0];
    const float* emb_W    = (const float*)d_in[1];
    const float* emb_b    = (const float*)d_in[2];
    const float* init_emb = (const float*)d_in[3];
    const float* eln_g    = (const float*)d_in[4];
    const float* eln_b    = (const float*)d_in[5];
    const float* Wih      = (const float*)d_in[6];
    const float* Whh      = (const float*)d_in[7];
    const float* bih      = (const float*)d_in[8];
    const float* bhh      = (const float*)d_in[9];
    const float* gln_g    = (const float*)d_in[10];
    const float* gln_b    = (const float*)d_in[11];
    const float* fc_W     = (const float*)d_in[12];
    const float* fc_b     = (const float*)d_in[13];
    float* out = (float*)d_out;

    cudaFuncSetAttribute(gru_kernel, cudaFuncAttributeMaxDynamicSharedMemorySize, 65536);
    cudaFuncSetAttribute(fc_kernel,  cudaFuncAttributeMaxDynamicSharedMemorySize, 36864);

    const int NPK = NWHH + NWIH + NEMB + NFC + 4 * Hn;
    pack_all<<<(NPK + 255) / 256, 256>>>(Whh, Wih, emb_W, fc_W, bih, bhh);
    step0_kernel<<<1, 512>>>(init_emb, eln_g, eln_b, Wih, bih, bhh);
    gh1_kernel<<<192, 256>>>(Whh);
    embed_kernel<<<dim3(2, 128), 256>>>(msg);
    lnx_kernel<<<16384 / 8, 256>>>(emb_b, eln_g, eln_b);
    for (int t = 1; t < Tn; t++)
        gru_kernel<<<dim3(Hn / 64, Bn / 64), 256, 65536>>>(t);
    hln_kernel<<<Bn / 8, 256>>>(gln_g, gln_b);
    fc_kernel<<<dim3(On / 64, Bn / 128), 256, 36864>>>(fc_b, out);
}

// round 13
// speedup vs baseline: 1.0878x; 1.0878x over previous
#include <cuda_runtime.h>
#include <cstdint>

#define Bn 4096
#define Tn 5
#define Vn 8192
#define En 32
#define Hn 512
#define On 1024

// packed f16x2 words, fragment order: word s in 32k-chunk, kw=(s>>2)+(s&3)*4
__device__ __align__(16) uint32_t d_Xp[Tn * Bn * 16];
__device__ __align__(16) float    d_hA[Bn * Hn];
__device__ __align__(16) float    d_hB[Bn * Hn];
__device__ __align__(16) uint32_t d_hpA[Bn * 256];
__device__ __align__(16) uint32_t d_hpB[Bn * 256];
__device__ __align__(16) uint32_t d_hlnp[Bn * 256];
__device__ __align__(16) uint32_t d_pWhh[16 * 3 * 512 * 16];
__device__ __align__(16) uint32_t d_pWih[3 * 512 * 16];
__device__ __align__(16) uint32_t d_pEmb[256 * 32 * 16];
__device__ __align__(16) uint32_t d_pFc[16 * 1024 * 16];
__device__ __align__(16) float    d_pBias[4 * Hn];
__device__ __align__(16) float    d_embP[2 * 16384 * 32];
__device__ __align__(16) float    d_h1[Hn];        // uniform h after step 0
__device__ __align__(16) float    d_gh1[3 * Hn];   // Whh @ h1 (uniform)

__device__ __forceinline__ uint32_t f2h2(float lo, float hi) {
    uint32_t r; asm volatile("cvt.rn.f16x2.f32 %0, %1, %2;" : "=r"(r) : "f"(hi), "f"(lo));
    return r;
}
__device__ __forceinline__ void mmah(float c[4], uint32_t a0, uint32_t a1, uint32_t a2,
                                     uint32_t a3, uint32_t b0, uint32_t b1) {
    asm volatile(
        "mma.sync.aligned.m16n8k16.row.col.f32.f16.f16.f32 "
        "{%0,%1,%2,%3}, {%4,%5,%6,%7}, {%8,%9}, {%0,%1,%2,%3};"
        : "+f"(c[0]), "+f"(c[1]), "+f"(c[2]), "+f"(c[3])
        : "r"(a0), "r"(a1), "r"(a2), "r"(a3), "r"(b0), "r"(b1));
}
__device__ __forceinline__ float sigm(float x) { return 1.f / (1.f + __expf(-x)); }
__device__ __forceinline__ float tanh_fast(float x) { return 1.f - 2.f / (1.f + __expf(2.f * x)); }
__device__ __forceinline__ void cp16(uint32_t dst, const void* src) {
    asm volatile("cp.async.cg.shared.global [%0], [%1], 16;" :: "r"(dst), "l"(src));
}
__device__ __forceinline__ void cp_commit() { asm volatile("cp.async.commit_group;"); }
template <int N> __device__ __forceinline__ void cp_wait() {
    asm volatile("cp.async.wait_group %0;" :: "n"(N));
}
__device__ __forceinline__ uint32_t smem_u32(const void* p) {
    return (uint32_t)__cvta_generic_to_shared(p);
}
__device__ __forceinline__ int sofkw(int kw) { return (kw & 3) * 4 + (kw >> 2); }

// ---------------- fused pack ----------------------------------------------------
#define NWHH (16 * 3 * 512 * 16)
#define NWIH (3 * 512 * 16)
#define NEMB (256 * 32 * 16)
#define NFC  (16 * 1024 * 16)
__global__ void pack_all(const float* __restrict__ Whh, const float* __restrict__ Wih,
                         const float* __restrict__ embW, const float* __restrict__ fcW,
                         const float* __restrict__ bih, const float* __restrict__ bhh) {
    int idx = blockIdx.x * 256 + threadIdx.x;
    if (idx < NWHH) {
        int s = idx & 15; int n = (idx >> 4) & 511; int u = idx >> 13;
        int gt = u % 3, it = u / 3;
        int kw = (s >> 2) + (s & 3) * 4; int k = it * 32 + 2 * kw;
        const float* p = Whh + (size_t)(gt * Hn + n) * Hn + k;
        d_pWhh[idx] = f2h2(p[0], p[1]);
    } else if (idx < NWHH + NWIH) {
        int i2 = idx - NWHH;
        int s = i2 & 15; int n = (i2 >> 4) & 511; int gt = i2 >> 13;
        int kw = (s >> 2) + (s & 3) * 4;
        const float* p = Wih + (size_t)(gt * Hn + n) * En + 2 * kw;
        d_pWih[i2] = f2h2(p[0], p[1]);
    } else if (idx < NWHH + NWIH + NEMB) {
        int i2 = idx - (NWHH + NWIH);
        int s = i2 & 15; int n = (i2 >> 4) & 31; int it = i2 >> 9;
        int kw = (s >> 2) + (s & 3) * 4; int k = it * 32 + 2 * kw;
        const float* p = embW + (size_t)n * Vn + k;
        d_pEmb[i2] = f2h2(p[0], p[1]);
    } else if (idx < NWHH + NWIH + NEMB + NFC) {
        int i2 = idx - (NWHH + NWIH + NEMB);
        int s = i2 & 15; int n = (i2 >> 4) & 1023; int it = i2 >> 14;
        int kw = (s >> 2) + (s & 3) * 4; int k = it * 32 + 2 * kw;
        const float* p = fcW + (size_t)n * Hn + k;
        d_pFc[i2] = f2h2(p[0], p[1]);
    } else if (idx < NWHH + NWIH + NEMB + NFC + 4 * Hn) {
        int i2 = idx - (NWHH + NWIH + NEMB + NFC);
        int j = i2 & 511, wh = i2 >> 9;
        d_pBias[i2] = (wh == 0) ? bih[j] + bhh[j]
                    : (wh == 1) ? bih[Hn + j] + bhh[Hn + j]
                    : (wh == 2) ? bih[2 * Hn + j] : bhh[2 * Hn + j];
    }
}

// ---------------- step 0: h1 (batch-uniform 512-vector), all f32 ------------------
__global__ void __launch_bounds__(512) step0_kernel(
    const float* __restrict__ init_emb, const float* __restrict__ eg,
    const float* __restrict__ ebeta, const float* __restrict__ Wih,
    const float* __restrict__ bih, const float* __restrict__ bhh) {
    __shared__ float x0[32];
    int tid = threadIdx.x;
    if (tid < 32) {
        float v = init_emb[tid];
        float s = v, sq = v * v;
        #pragma unroll
        for (int o = 16; o; o >>= 1) {
            s += __shfl_xor_sync(~0u, s, o); sq += __shfl_xor_sync(~0u, sq, o);
        }
        float m = s / 32.f, rs = rsqrtf(sq / 32.f - m * m + 1e-5f);
        x0[tid] = (v - m) * rs * eg[tid] + ebeta[tid];
    }
    __syncthreads();
    int j = tid;
    float gr = 0.f, gz = 0.f, gn = 0.f;
    #pragma unroll
    for (int k = 0; k < 32; k++) {
        float xv = x0[k];
        gr += Wih[(size_t)j * En + k] * xv;
        gz += Wih[(size_t)(Hn + j) * En + k] * xv;
        gn += Wih[(size_t)(2 * Hn + j) * En + k] * xv;
    }
    float r_ = sigm(gr + bih[j] + bhh[j]);
    float z_ = sigm(gz + bih[Hn + j] + bhh[Hn + j]);
    float n_ = tanh_fast(gn + bih[2 * Hn + j] + r_ * bhh[2 * Hn + j]);
    d_h1[j] = (1.f - z_) * n_;
}

// ---------------- gh1 = Whh @ h1 (1536x512 f32 GEMV, warp per row) ------------------
__global__ void __launch_bounds__(256) gh1_kernel(const float* __restrict__ Whh) {
    int row = blockIdx.x * 8 + (threadIdx.x >> 5);   // 0..1535
    int lane = threadIdx.x & 31;
    const float* wr = Whh + (size_t)row * Hn;
    float s = 0.f;
    #pragma unroll
    for (int i = 0; i < 4; i++) {
        float4 w = *(const float4*)(wr + lane * 4 + i * 128);
        float4 h = *(const float4*)(d_h1 + lane * 4 + i * 128);
        s += w.x * h.x + w.y * h.y + w.z * h.z + w.w * h.w;
    }
    #pragma unroll
    for (int o = 16; o; o >>= 1) s += __shfl_xor_sync(~0u, s, o);
    if (lane == 0) d_gh1[row] = s;
}

// ---------------- embed: K-split x2, BM=64, 128 thr, 4-stage dist-3 (r11 exact) -----
__global__ void __launch_bounds__(128, 5) embed_kernel(const float* __restrict__ msg) {
    extern __shared__ uint32_t sm[];
    const int tid = threadIdx.x, warp = tid >> 5, lane = tid & 31;
    const int gq = lane >> 2, tq = lane & 3;
    const int ks = blockIdx.x;
    const int m0 = blockIdx.y * 64;
    const int kbase = ks * 128;
    const uint32_t smb = smem_u32(sm);

    auto prefetch = [&](int it) {
        uint32_t ab = smb + (it & 3) * 10240, bb = ab + 8192;
        #pragma unroll
        for (int j = 0; j < 4; j++) {
            int id = tid + j * 128; int row = id >> 3, cc = id & 7;
            int m = m0 + row; int b = m >> 2, tt = m & 3;
            cp16(ab + row * 128 + ((cc * 16) ^ ((row & 3) * 32)),
                 msg + ((size_t)b * Tn + tt) * Vn + (kbase + it) * 32 + cc * 4);
        }
        { int row = tid >> 2, cc = tid & 3;
          cp16(bb + row * 64 + cc * 16,
               d_pEmb + ((size_t)(kbase + it) * 32 + row) * 16 + cc * 4); }
        cp_commit();
    };

    float acc[4][4] = {};
    prefetch(0); prefetch(1); prefetch(2);
    for (int it = 0; it < 128; ++it) {
        if (it <= 125) cp_wait<2>(); else if (it == 126) cp_wait<1>(); else cp_wait<0>();
        __syncthreads();
        if (it + 3 < 128) prefetch(it + 3);
        const uint32_t* A = sm + (it & 3) * 2560;
        const uint32_t* B = A + 2048;
        int r0 = warp * 16 + gq, r1 = r0 + 8;
        uint4 Bw[4];
        #pragma unroll
        for (int nb = 0; nb < 4; nb++) Bw[nb] = *(const uint4*)&B[(nb * 8 + gq) * 16 + tq * 4];
        #pragma unroll
        for (int s = 0; s < 2; s++) {
            float2 f00 = *(const float2*)&A[r0 * 32 + ((s * 16 + tq * 2)     ^ ((r0 & 3) * 8))];
            float2 f01 = *(const float2*)&A[r0 * 32 + ((s * 16 + 8 + tq * 2) ^ ((r0 & 3) * 8))];
            float2 f10 = *(const float2*)&A[r1 * 32 + ((s * 16 + tq * 2)     ^ ((r1 & 3) * 8))];
            float2 f11 = *(const float2*)&A[r1 * 32 + ((s * 16 + 8 + tq * 2) ^ ((r1 & 3) * 8))];
            uint32_t a0 = f2h2(f00.x, f00.y), a2 = f2h2(f01.x, f01.y);
            uint32_t a1 = f2h2(f10.x, f10.y), a3 = f2h2(f11.x, f11.y);
            #pragma unroll
            for (int nb = 0; nb < 4; nb++)
                mmah(acc[nb], a0, a1, a2, a3, s ? Bw[nb].z : Bw[nb].x, s ? Bw[nb].w : Bw[nb].y);
        }
        __syncthreads();
    }

    float* dst = d_embP + (size_t)ks * 16384 * 32;
    int mr0 = m0 + warp * 16 + gq, mr1 = mr0 + 8;
    #pragma unroll
    for (int nb = 0; nb < 4; nb++) {
        int col = nb * 8 + 2 * tq;
        *(float2*)&dst[(size_t)mr0 * 32 + col] = make_float2(acc[nb][0], acc[nb][1]);
        *(float2*)&dst[(size_t)mr1 * 32 + col] = make_float2(acc[nb][2], acc[nb][3]);
    }
}

// ---------------- lnx: sum 2 partials + bias + LN + pack ---------------------------
__global__ void __launch_bounds__(256) lnx_kernel(const float* __restrict__ eb,
                                                  const float* __restrict__ gw,
                                                  const float* __restrict__ bw) {
    int row = blockIdx.x * 8 + (threadIdx.x >> 5);
    int lane = threadIdx.x & 31;
    float v = d_embP[(size_t)row * 32 + lane]
            + d_embP[(size_t)16384 * 32 + (size_t)row * 32 + lane] + eb[lane];
    float s = v, sq = v * v;
    #pragma unroll
    for (int o = 16; o; o >>= 1) {
        s += __shfl_xor_sync(~0u, s, o); sq += __shfl_xor_sync(~0u, sq, o);
    }
    float m = s / 32.f, rs = rsqrtf(sq / 32.f - m * m + 1e-5f);
    float o1 = (v - m) * rs * gw[lane] + bw[lane];
    float o2 = __shfl_down_sync(~0u, o1, 1);
    if (!(lane & 1)) {
        int bb = row >> 2, tt = row & 3;
        d_Xp[((size_t)(tt + 1) * Bn + bb) * 16 + sofkw(lane >> 1)] = f2h2(o1, o2);
    }
}

// ---------------- GRU fp16 (t = 1..4): BM=64, BN=64x3, 256 thr, 4-stage, 1 sync -----
__global__ void __launch_bounds__(256, 2) gru_kernel(int t) {
    extern __shared__ uint32_t sm[];
    const uint32_t smb = smem_u32(sm);
    const int tid = threadIdx.x, warp = tid >> 5, lane = tid & 31;
    const int gq = lane >> 2, tq = lane & 3;
    const int n0 = blockIdx.x * 64, m0 = blockIdx.y * 64;
    const int mo = (warp & 1) * 32, no = (warp >> 1) * 16;
    const float*    hold  = (t & 1) ? d_hB  : d_hA;
    float*          hnew  = (t & 1) ? d_hA  : d_hB;
    const uint32_t* hpold = (t & 1) ? d_hpB : d_hpA;
    uint32_t*       hpnew = (t & 1) ? d_hpA : d_hpB;
    const int NITER = (t == 1) ? 1 : 17;

    const int arow = tid >> 2, acc4 = tid & 3;

    auto prefetch0 = [&]() {
        uint32_t base = smb;
        cp16(base + arow * 64 + acc4 * 16,
             d_Xp + ((size_t)t * Bn + m0 + arow) * 16 + acc4 * 4);
        #pragma unroll
        for (int j = 0; j < 3; j++) {
            int id = tid + j * 256;
            int brow = id >> 2, cc = id & 3;
            int gt = brow >> 6, row = brow & 63;
            cp16(base + 4096 + brow * 64 + cc * 16,
                 d_pWih + ((size_t)gt * Hn + n0 + row) * 16 + cc * 4);
        }
        cp_commit();
    };
    auto prefetchH = [&](int it) {
        uint32_t base = smb + (it & 3) * 16384;
        cp16(base + arow * 64 + acc4 * 16,
             hpold + (size_t)(m0 + arow) * 256 + (it - 1) * 16 + acc4 * 4);
        #pragma unroll
        for (int j = 0; j < 3; j++) {
            int id = tid + j * 256;
            int brow = id >> 2, cc = id & 3;
            int gt = brow >> 6, row = brow & 63;
            cp16(base + 4096 + brow * 64 + cc * 16,
                 d_pWhh + (((size_t)(it - 1) * 3 + gt) * Hn + n0 + row) * 16 + cc * 4);
        }
        cp_commit();
    };

    float ar[2][2][4] = {}, az[2][2][4] = {}, anx[2][2][4] = {}, anh[2][2][4] = {};
    prefetch0();
    if (NITER > 1) { prefetchH(1); prefetchH(2); }
    for (int it = 0; it < NITER; ++it) {
        int rem = NITER - 1 - it;
        if (rem >= 2) cp_wait<2>(); else if (rem == 1) cp_wait<1>(); else cp_wait<0>();
        __syncthreads();
        if (it + 3 < NITER) prefetchH(it + 3);
        const uint32_t* A = sm + (it & 3) * 4096;
        const uint32_t* B = A + 1024;
        uint4 Af[4];
        Af[0] = *(const uint4*)&A[(mo + gq) * 16 + tq * 4];
        Af[1] = *(const uint4*)&A[(mo + gq + 8) * 16 + tq * 4];
        Af[2] = *(const uint4*)&A[(mo + 16 + gq) * 16 + tq * 4];
        Af[3] = *(const uint4*)&A[(mo + 24 + gq) * 16 + tq * 4];
        auto dog = [&](float (&acc)[2][2][4], int g) {
            #pragma unroll
            for (int nb = 0; nb < 2; nb++) {
                uint4 Bf = *(const uint4*)&B[(g * 64 + no + nb * 8 + gq) * 16 + tq * 4];
                mmah(acc[0][nb], Af[0].x, Af[1].x, Af[0].y, Af[1].y, Bf.x, Bf.y);
                mmah(acc[1][nb], Af[2].x, Af[3].x, Af[2].y, Af[3].y, Bf.x, Bf.y);
                mmah(acc[0][nb], Af[0].z, Af[1].z, Af[0].w, Af[1].w, Bf.z, Bf.w);
                mmah(acc[1][nb], Af[2].z, Af[3].z, Af[2].w, Af[3].w, Bf.z, Bf.w);
            }
        };
        dog(ar, 0); dog(az, 1);
        if (it == 0) dog(anx, 2); else dog(anh, 2);
    }

    #pragma unroll
    for (int mf = 0; mf < 2; ++mf)
    #pragma unroll
    for (int nb = 0; nb < 2; ++nb) {
        int j0 = n0 + no + nb * 8 + 2 * tq;
        int kw = (j0 & 31) >> 1, sw = sofkw(kw), ch = j0 >> 5;
        #pragma unroll
        for (int half = 0; half < 2; ++half) {
            int brow = m0 + mo + mf * 16 + gq + half * 8;
            float hv[2];
            #pragma unroll
            for (int c2 = 0; c2 < 2; ++c2) {
                int idx = half * 2 + c2, j = j0 + c2;
                float ghr = 0.f, ghz = 0.f, ghn = 0.f, hprev;
                if (t == 1) {
                    ghr = d_gh1[j]; ghz = d_gh1[Hn + j]; ghn = d_gh1[2 * Hn + j];
                    hprev = d_h1[j];
                } else {
                    hprev = hold[(size_t)brow * Hn + j];
                }
                float r_ = sigm(ar[mf][nb][idx] + d_pBias[j] + ghr);
                float z_ = sigm(az[mf][nb][idx] + d_pBias[Hn + j] + ghz);
                float n_ = tanh_fast(anx[mf][nb][idx] + d_pBias[2 * Hn + j]
                                     + r_ * (anh[mf][nb][idx] + d_pBias[3 * Hn + j] + ghn));
                hv[c2] = (1.f - z_) * n_ + z_ * hprev;
                hnew[(size_t)brow * Hn + j] = hv[c2];
            }
            hpnew[(size_t)brow * 256 + ch * 16 + sw] = f2h2(hv[0], hv[1]);
        }
    }
}

// ---------------- LN(h_last) -> packed f16 ------------------------------------------
__global__ void __launch_bounds__(256) hln_kernel(const float* __restrict__ g,
                                                  const float* __restrict__ be) {
    int row = blockIdx.x * 8 + (threadIdx.x >> 5);
    int lane = threadIdx.x & 31;
    const float* hp = d_hB + (size_t)row * Hn;
    float4 v[4]; float s = 0.f, sq = 0.f;
    #pragma unroll
    for (int i = 0; i < 4; i++) {
        v[i] = *(const float4*)(hp + lane * 4 + i * 128);
        s += v[i].x + v[i].y + v[i].z + v[i].w;
        sq += v[i].x * v[i].x + v[i].y * v[i].y + v[i].z * v[i].z + v[i].w * v[i].w;
    }
    #pragma unroll
    for (int o = 16; o; o >>= 1) {
        s += __shfl_xor_sync(~0u, s, o); sq += __shfl_xor_sync(~0u, sq, o);
    }
    float m = s / 512.f, rs = rsqrtf(sq / 512.f - m * m + 1e-5f);
    uint32_t* op = d_hlnp + (size_t)row * 256;
    #pragma unroll
    for (int i = 0; i < 4; i++) {
        int c = lane * 4 + i * 128;
        int ch = c >> 5;
        float o0 = (v[i].x - m) * rs * g[c] + be[c];
        float o1 = (v[i].y - m) * rs * g[c + 1] + be[c + 1];
        float o2 = (v[i].z - m) * rs * g[c + 2] + be[c + 2];
        float o3 = (v[i].w - m) * rs * g[c + 3] + be[c + 3];
        int kw = (c & 31) >> 1;
        op[ch * 16 + sofkw(kw)]     = f2h2(o0, o1);
        op[ch * 16 + sofkw(kw + 1)] = f2h2(o2, o3);
    }
}

// ---------------- fc fp16: BM=128, BN=64, 256 thr, 3-stage, 1 sync -------------------
__global__ void __launch_bounds__(256, 1) fc_kernel(const float* __restrict__ bias,
                                                    float* __restrict__ out) {
    extern __shared__ uint32_t sm[];
    const uint32_t smb = smem_u32(sm);
    const int tid = threadIdx.x, warp = tid >> 5, lane = tid & 31;
    const int gq = lane >> 2, tq = lane & 3;
    const int n0 = blockIdx.x * 64, m0 = blockIdx.y * 128;
    const int mo = (warp & 3) * 32, no = (warp >> 2) * 32;

    auto prefetch = [&](int it) {
        uint32_t base = smb + (it % 3) * 12288;
        #pragma unroll
        for (int j = 0; j < 2; j++) {
            int id = tid + j * 256; int row = id >> 2, cc = id & 3;
            cp16(base + row * 64 + cc * 16,
                 d_hlnp + (size_t)(m0 + row) * 256 + it * 16 + cc * 4);
        }
        { int row = tid >> 2, cc = tid & 3;
          cp16(base + 8192 + row * 64 + cc * 16,
               d_pFc + ((size_t)it * On + n0 + row) * 16 + cc * 4); }
        cp_commit();
    };

    float acc[2][4][4] = {};
    prefetch(0); prefetch(1);
    for (int it = 0; it < 16; ++it) {
        if (it <= 13) cp_wait<1>(); else cp_wait<0>();
        __syncthreads();
        if (it + 2 < 16) prefetch(it + 2);
        const uint32_t* A = sm + (it % 3) * 3072;
        const uint32_t* B = A + 2048;
        uint4 Af[4];
        Af[0] = *(const uint4*)&A[(mo + gq) * 16 + tq * 4];
        Af[1] = *(const uint4*)&A[(mo + gq + 8) * 16 + tq * 4];
        Af[2] = *(const uint4*)&A[(mo + 16 + gq) * 16 + tq * 4];
        Af[3] = *(const uint4*)&A[(mo + 24 + gq) * 16 + tq * 4];
        #pragma unroll
        for (int nb = 0; nb < 4; nb++) {
            uint4 Bf = *(const uint4*)&B[(no + nb * 8 + gq) * 16 + tq * 4];
            mmah(acc[0][nb], Af[0].x, Af[1].x, Af[0].y, Af[1].y, Bf.x, Bf.y);
            mmah(acc[1][nb], Af[2].x, Af[3].x, Af[2].y, Af[3].y, Bf.x, Bf.y);
            mmah(acc[0][nb], Af[0].z, Af[1].z, Af[0].w, Af[1].w, Bf.z, Bf.w);
            mmah(acc[1][nb], Af[2].z, Af[3].z, Af[2].w, Af[3].w, Bf.z, Bf.w);
        }
    }
    #pragma unroll
    for (int mf = 0; mf < 2; ++mf)
    #pragma unroll
    for (int nb = 0; nb < 4; ++nb)
    #pragma unroll
    for (int idx = 0; idx < 4; ++idx) {
        int row = m0 + mo + mf * 16 + gq + (idx >> 1) * 8;
        int j = n0 + no + nb * 8 + 2 * tq + (idx & 1);
        out[(size_t)row * On + j] = sigm(acc[mf][nb][idx] + bias[j]);
    }
}

// ---------------- launch --------------------------------------------------------------
extern "C" void kernel_launch(void* const* d_in, const int* in_sizes, int n_in,
                              void* d_out, int out_size) {
    const float* msg      = (const float*)d_in[0];
    const float* emb_W    = (const float*)d_in[1];
    const float* emb_b    = (const float*)d_in[2];
    const float* init_emb = (const float*)d_in[3];
    const float* eln_g    = (const float*)d_in[4];
    const float* eln_b    = (const float*)d_in[5];
    const float* Wih      = (const float*)d_in[6];
    const float* Whh      = (const float*)d_in[7];
    const float* bih      = (const float*)d_in[8];
    const float* bhh      = (const float*)d_in[9];
    const float* gln_g    = (const float*)d_in[10];
    const float* gln_b    = (const float*)d_in[11];
    const float* fc_W     = (const float*)d_in[12];
    const float* fc_b     = (const float*)d_in[13];
    float* out = (float*)d_out;

    cudaFuncSetAttribute(embed_kernel, cudaFuncAttributeMaxDynamicSharedMemorySize, 40960);
    cudaFuncSetAttribute(gru_kernel,   cudaFuncAttributeMaxDynamicSharedMemorySize, 65536);
    cudaFuncSetAttribute(fc_kernel,    cudaFuncAttributeMaxDynamicSharedMemorySize, 36864);

    const int NPK = NWHH + NWIH + NEMB + NFC + 4 * Hn;
    pack_all<<<(NPK + 255) / 256, 256>>>(Whh, Wih, emb_W, fc_W, bih, bhh);
    step0_kernel<<<1, 512>>>(init_emb, eln_g, eln_b, Wih, bih, bhh);
    gh1_kernel<<<192, 256>>>(Whh);
    embed_kernel<<<dim3(2, 256), 128, 40960>>>(msg);
    lnx_kernel<<<16384 / 8, 256>>>(emb_b, eln_g, eln_b);
    for (int t = 1; t < Tn; t++)
        gru_kernel<<<dim3(Hn / 64, Bn / 64), 256, 65536>>>(t);
    hln_kernel<<<Bn / 8, 256>>>(gln_g, gln_b);
    fc_kernel<<<dim3(On / 64, Bn / 128), 256, 36864>>>(fc_b, out);
}